// round 9
// baseline (speedup 1.0000x reference)
#include <cuda_runtime.h>

// out[n,i] = sum_{m<K} W[i, m*D+i] * h_r[n, m*D+i] + b[i]
// N=8192, D=1024, K=8. HBM streaming: 256MB read + 32MB write.
// Single fused kernel: cooperative W-diagonal gather + sense-reversing
// grid barrier (single resident wave, occupancy-clamped -> deadlock-free),
// then the proven R8 streaming loop (MLP=8, __ldcs reads, write-back
// stores, pointer strength reduction). No second launch, no PDL gap.

constexpr int D = 1024;
constexpr int K = 8;
constexpr int KD = K * D;           // 8192
constexpr int THREADS = 256;        // thread t owns output cols [4t, 4t+4)
constexpr int CTAS_PER_SM = 4;
constexpr int MAX_GRID = 1024;

// Gathered diagonal of W: g_wd[m*D + i] = W[i, m*D + i]
__device__ float g_wd[KD];

// Grid barrier state (sense-reversing; self-resetting across graph replays).
__device__ unsigned int g_arrive = 0;
__device__ unsigned int g_gen = 0;

__global__ __launch_bounds__(THREADS, CTAS_PER_SM)
void imputation_kernel(const float* __restrict__ h_r,
                       const float* __restrict__ W,
                       const float* __restrict__ b,
                       float* __restrict__ out,
                       int n_rows) {
    __shared__ float4 wd4[K][THREADS];

    const int t = threadIdx.x;
    const int nctas = gridDim.x;

    // ---- Phase 1: cooperative scattered gather of the W diagonal ----
    // Each CTA grabs a contiguous chunk of the 8192 diagonal elements.
    {
        const int chunk = (KD + nctas - 1) / nctas;
        const int base = blockIdx.x * chunk;
        for (int j = t; j < chunk; j += THREADS) {
            const int idx = base + j;
            if (idx < KD) {
                const int m = idx >> 10;
                const int i = idx & (D - 1);
                g_wd[idx] = __ldg(&W[(size_t)i * KD + m * D + i]);
            }
        }
    }
    __threadfence();   // publish g_wd before arriving

    // ---- Grid barrier (single resident wave; clamped by host) ----
    if (t == 0) {
        const unsigned int gen0 = *(volatile unsigned int*)&g_gen;
        const unsigned int old = atomicAdd(&g_arrive, 1u);
        if (old == (unsigned int)nctas - 1u) {
            g_arrive = 0;              // reset for next graph replay
            __threadfence();
            atomicAdd(&g_gen, 1u);     // release waiters
        } else {
            while (*(volatile unsigned int*)&g_gen == gen0) {
                __nanosleep(64);
            }
        }
    }
    __syncthreads();
    __threadfence();   // acquire: g_wd writes visible

    // ---- Load gathered diagonal (L2-resident) + bias into smem/regs ----
    const float4* gw4 = reinterpret_cast<const float4*>(g_wd);
    #pragma unroll
    for (int m = 0; m < K; m++) {
        wd4[m][t] = gw4[m * THREADS + t];
    }
    const float4 breg = reinterpret_cast<const float4*>(b)[t];
    __syncthreads();

    // ---- Phase 2: HBM-wall streaming loop (proven R8 config) ----
    const float4* __restrict__ hp =
        reinterpret_cast<const float4*>(h_r) + (size_t)blockIdx.x * (KD / 4) + t;
    float4* __restrict__ op =
        reinterpret_cast<float4*>(out) + (size_t)blockIdx.x * (D / 4) + t;
    const size_t h_step = (size_t)nctas * (KD / 4);
    const size_t o_step = (size_t)nctas * (D / 4);

    for (int n = blockIdx.x; n < n_rows; n += nctas, hp += h_step, op += o_step) {
        // 8 independent streaming (evict-first) loads in flight.
        float4 h[K];
        #pragma unroll
        for (int m = 0; m < K; m++) {
            h[m] = __ldcs(hp + m * (D / 4));
        }

        float4 acc = breg;
        #pragma unroll
        for (int m = 0; m < K; m++) {
            const float4 w = wd4[m][t];   // LDS.128, conflict-free
            acc.x = fmaf(h[m].x, w.x, acc.x);
            acc.y = fmaf(h[m].y, w.y, acc.y);
            acc.z = fmaf(h[m].z, w.z, acc.z);
            acc.w = fmaf(h[m].w, w.w, acc.w);
        }

        // Cached write-back store: dirty lines park in L2, flush in bursts.
        *op = acc;
    }
}

extern "C" void kernel_launch(void* const* d_in, const int* in_sizes, int n_in,
                              void* d_out, int out_size) {
    const float* h_r = (const float*)d_in[0];
    const float* W   = (const float*)d_in[1];
    const float* b   = (const float*)d_in[2];
    float* out       = (float*)d_out;

    const int n_rows = in_sizes[0] / KD;   // 8192

    // Deadlock-proof grid sizing: exactly one resident wave.
    static int grid_size = 0;   // host-side cache of a pure device property
    if (grid_size == 0) {
        int dev = 0, sms = 0, blocks_per_sm = 0;
        cudaGetDevice(&dev);
        cudaDeviceGetAttribute(&sms, cudaDevAttrMultiProcessorCount, dev);
        cudaOccupancyMaxActiveBlocksPerMultiprocessor(
            &blocks_per_sm, imputation_kernel, THREADS, 0);
        grid_size = sms * blocks_per_sm;
        if (grid_size > MAX_GRID) grid_size = MAX_GRID;
        if (grid_size < 1) grid_size = 1;
    }

    imputation_kernel<<<grid_size, THREADS>>>(h_r, W, b, out, n_rows);
}

// round 11
// speedup vs baseline: 1.0250x; 1.0250x over previous
#include <cuda_runtime.h>

// out[n,i] = sum_{m<K} W[i, m*D+i] * h_r[n, m*D+i] + b[i]
// N=8192, D=1024, K=8. 256MB read + 32MB write per call.
// Structure: tiny gather kernel + PDL-overlapped main kernel (proven best).
// This round: pin output lines in L2 via createpolicy(evict_last) +
// st.global.L2::cache_hint (the ptxas-legal form for .v4.f32) so the 32MB
// write stream stays L2-resident across graph replays.

constexpr int D = 1024;
constexpr int K = 8;
constexpr int KD = K * D;           // 8192
constexpr int THREADS = 256;        // thread t owns output cols [4t, 4t+4)
constexpr int CTAS_PER_SM = 4;
constexpr int NUM_SMS = 152;        // GB300
constexpr int GRID = CTAS_PER_SM * NUM_SMS;   // 608 persistent CTAs

// Gathered diagonal of W: g_wd[m*D + i] = W[i, m*D + i]
__device__ float g_wd[KD];

__global__ void gather_wdiag_kernel(const float* __restrict__ W) {
    const int idx = blockIdx.x * blockDim.x + threadIdx.x;
    if (idx < KD) {
        const int m = idx >> 10;
        const int i = idx & (D - 1);
        g_wd[idx] = W[(size_t)i * KD + m * D + i];
    }
}

__device__ __forceinline__ unsigned long long make_evict_last_policy() {
    unsigned long long policy;
    asm("createpolicy.fractional.L2::evict_last.b64 %0, 1.0;" : "=l"(policy));
    return policy;
}

__device__ __forceinline__ void st_evict_last(float4* p, float4 v,
                                              unsigned long long policy) {
    asm volatile(
        "st.global.L2::cache_hint.v4.f32 [%0], {%1, %2, %3, %4}, %5;"
        :: "l"(p), "f"(v.x), "f"(v.y), "f"(v.z), "f"(v.w), "l"(policy)
        : "memory");
}

__global__ __launch_bounds__(THREADS, CTAS_PER_SM)
void imputation_kernel(const float* __restrict__ h_r,
                       const float* __restrict__ b,
                       float* __restrict__ out,
                       int n_rows) {
    __shared__ float4 wd4[K][THREADS];

    const int t = threadIdx.x;

    // --- PDL prologue: everything NOT depending on g_wd ---
    const float4 breg = reinterpret_cast<const float4*>(b)[t];
    const unsigned long long policy = make_evict_last_policy();

    // Row-base pointers, advanced by GRID rows per iteration.
    const float4* __restrict__ hp =
        reinterpret_cast<const float4*>(h_r) + (size_t)blockIdx.x * (KD / 4) + t;
    float4* __restrict__ op =
        reinterpret_cast<float4*>(out) + (size_t)blockIdx.x * (D / 4) + t;
    constexpr size_t H_STEP = (size_t)GRID * (KD / 4);
    constexpr size_t O_STEP = (size_t)GRID * (D / 4);

    // Wait for gather_wdiag_kernel to complete (PDL dependency).
    cudaGridDependencySynchronize();

    // Coalesced load of the pre-gathered diagonal (8 KB, L2-resident).
    const float4* gw4 = reinterpret_cast<const float4*>(g_wd);
    #pragma unroll
    for (int m = 0; m < K; m++) {
        wd4[m][t] = gw4[m * THREADS + t];
    }
    __syncthreads();

    // Persistent grid-stride over rows (608 CTAs, 4/SM everywhere).
    for (int n = blockIdx.x; n < n_rows; n += GRID, hp += H_STEP, op += O_STEP) {
        // 8 independent streaming (evict-first) loads in flight.
        float4 h[K];
        #pragma unroll
        for (int m = 0; m < K; m++) {
            h[m] = __ldcs(hp + m * (D / 4));
        }

        float4 acc = breg;
        #pragma unroll
        for (int m = 0; m < K; m++) {
            const float4 w = wd4[m][t];   // LDS.128, conflict-free
            acc.x = fmaf(h[m].x, w.x, acc.x);
            acc.y = fmaf(h[m].y, w.y, acc.y);
            acc.z = fmaf(h[m].z, w.z, acc.z);
            acc.w = fmaf(h[m].w, w.w, acc.w);
        }

        // Output lines hinted evict_last: the 32MB output stream stays
        // L2-resident across replays -> DRAM sees mostly the 256MB reads.
        st_evict_last(op, acc, policy);
    }
}

extern "C" void kernel_launch(void* const* d_in, const int* in_sizes, int n_in,
                              void* d_out, int out_size) {
    const float* h_r = (const float*)d_in[0];
    const float* W   = (const float*)d_in[1];
    const float* b   = (const float*)d_in[2];
    float* out       = (float*)d_out;

    const int n_rows = in_sizes[0] / KD;   // 8192

    gather_wdiag_kernel<<<(KD + 255) / 256, 256>>>(W);

    // PDL: main kernel boots + runs g_wd-independent prologue while the
    // gather kernel finishes.
    cudaLaunchConfig_t cfg = {};
    cfg.gridDim = dim3(GRID, 1, 1);
    cfg.blockDim = dim3(THREADS, 1, 1);
    cfg.dynamicSmemBytes = 0;
    cfg.stream = 0;
    cudaLaunchAttribute attrs[1];
    attrs[0].id = cudaLaunchAttributeProgrammaticStreamSerialization;
    attrs[0].val.programmaticStreamSerializationAllowed = 1;
    cfg.attrs = attrs;
    cfg.numAttrs = 1;
    cudaLaunchKernelEx(&cfg, imputation_kernel, h_r, b, out, n_rows);
}

// round 12
// speedup vs baseline: 1.0257x; 1.0006x over previous
#include <cuda_runtime.h>

// out[n,i] = sum_{m<K} W[i, m*D+i] * h_r[n, m*D+i] + b[i]
// N=8192, D=1024, K=8. 256MB read + 32MB write per call.
// Best-known body (R8: 608 persistent CTAs, MLP=8 __ldcs reads, plain
// write-back stores, strength-reduced pointers) + deterministic PDL:
// the gather kernel fires cudaTriggerProgrammaticLaunchCompletion()
// immediately so the main kernel boots while the gather runs.

constexpr int D = 1024;
constexpr int K = 8;
constexpr int KD = K * D;           // 8192
constexpr int THREADS = 256;        // thread t owns output cols [4t, 4t+4)
constexpr int CTAS_PER_SM = 4;
constexpr int NUM_SMS = 152;        // GB300
constexpr int GRID = CTAS_PER_SM * NUM_SMS;   // 608 persistent CTAs

// Gathered diagonal of W: g_wd[m*D + i] = W[i, m*D + i]
__device__ float g_wd[KD];

__global__ void gather_wdiag_kernel(const float* __restrict__ W) {
    // Release the dependent launch immediately: the main kernel's boot +
    // g_wd-independent prologue overlap this kernel's scattered loads.
    cudaTriggerProgrammaticLaunchCompletion();

    const int idx = blockIdx.x * blockDim.x + threadIdx.x;
    if (idx < KD) {
        const int m = idx >> 10;
        const int i = idx & (D - 1);
        g_wd[idx] = __ldg(&W[(size_t)i * KD + m * D + i]);
    }
}

__global__ __launch_bounds__(THREADS, CTAS_PER_SM)
void imputation_kernel(const float* __restrict__ h_r,
                       const float* __restrict__ b,
                       float* __restrict__ out,
                       int n_rows) {
    __shared__ float4 wd4[K][THREADS];

    const int t = threadIdx.x;

    // --- PDL prologue: everything NOT depending on g_wd ---
    const float4 breg = reinterpret_cast<const float4*>(b)[t];

    // Row-base pointers, advanced by GRID rows per iteration.
    const float4* __restrict__ hp =
        reinterpret_cast<const float4*>(h_r) + (size_t)blockIdx.x * (KD / 4) + t;
    float4* __restrict__ op =
        reinterpret_cast<float4*>(out) + (size_t)blockIdx.x * (D / 4) + t;
    constexpr size_t H_STEP = (size_t)GRID * (KD / 4);
    constexpr size_t O_STEP = (size_t)GRID * (D / 4);

    // Wait for gather_wdiag_kernel to fully complete.
    cudaGridDependencySynchronize();

    // Coalesced load of the pre-gathered diagonal (8 KB, L2-resident).
    const float4* gw4 = reinterpret_cast<const float4*>(g_wd);
    #pragma unroll
    for (int m = 0; m < K; m++) {
        wd4[m][t] = gw4[m * THREADS + t];
    }
    __syncthreads();

    // Persistent grid-stride over rows (608 CTAs, 4/SM everywhere).
    for (int n = blockIdx.x; n < n_rows; n += GRID, hp += H_STEP, op += O_STEP) {
        // 8 independent streaming (evict-first) loads in flight.
        float4 h[K];
        #pragma unroll
        for (int m = 0; m < K; m++) {
            h[m] = __ldcs(hp + m * (D / 4));
        }

        float4 acc = breg;
        #pragma unroll
        for (int m = 0; m < K; m++) {
            const float4 w = wd4[m][t];   // LDS.128, conflict-free
            acc.x = fmaf(h[m].x, w.x, acc.x);
            acc.y = fmaf(h[m].y, w.y, acc.y);
            acc.z = fmaf(h[m].z, w.z, acc.z);
            acc.w = fmaf(h[m].w, w.w, acc.w);
        }

        // Plain write-back store (best measured): dirty lines park in L2
        // and flush in bursts instead of interleaving with reads.
        *op = acc;
    }
}

extern "C" void kernel_launch(void* const* d_in, const int* in_sizes, int n_in,
                              void* d_out, int out_size) {
    const float* h_r = (const float*)d_in[0];
    const float* W   = (const float*)d_in[1];
    const float* b   = (const float*)d_in[2];
    float* out       = (float*)d_out;

    const int n_rows = in_sizes[0] / KD;   // 8192

    // Wider, shallower gather: 64 CTAs x 128 threads -> shorter critical path.
    gather_wdiag_kernel<<<64, 128>>>(W);

    // PDL: explicit early trigger in the gather kernel lets this launch
    // overlap the gather's execution, not just its tail.
    cudaLaunchConfig_t cfg = {};
    cfg.gridDim = dim3(GRID, 1, 1);
    cfg.blockDim = dim3(THREADS, 1, 1);
    cfg.dynamicSmemBytes = 0;
    cfg.stream = 0;
    cudaLaunchAttribute attrs[1];
    attrs[0].id = cudaLaunchAttributeProgrammaticStreamSerialization;
    attrs[0].val.programmaticStreamSerializationAllowed = 1;
    cfg.attrs = attrs;
    cfg.numAttrs = 1;
    cudaLaunchKernelEx(&cfg, imputation_kernel, h_r, b, out, n_rows);
}

// round 13
// speedup vs baseline: 1.0753x; 1.0484x over previous
#include <cuda_runtime.h>

// out[n,i] = sum_{m<K} W[i, m*D+i] * h_r[n, m*D+i] + b[i]
// N=8192, D=1024, K=8. HBM streaming: 256MB read + 32MB write.
// Converged configuration (best measured total, 47.1us):
//   608 persistent CTAs (4/SM), MLP=8 __ldcs streaming reads, plain
//   write-back stores (L2 write absorption), PDL-overlapped W-diag gather.
// Kernel body measures 45.7-46.3us = the HBM wall for this 8:1 fp32
// read/write mix (invariant across 7 shape/policy variants).

constexpr int D = 1024;
constexpr int K = 8;
constexpr int KD = K * D;           // 8192
constexpr int THREADS = 256;        // thread t owns output cols [4t, 4t+4)
constexpr int CTAS_PER_SM = 4;
constexpr int NUM_SMS = 152;        // GB300
constexpr int GRID = CTAS_PER_SM * NUM_SMS;   // 608 persistent CTAs

// Gathered diagonal of W: g_wd[m*D + i] = W[i, m*D + i]
__device__ float g_wd[KD];

__global__ void gather_wdiag_kernel(const float* __restrict__ W) {
    const int idx = blockIdx.x * blockDim.x + threadIdx.x;
    if (idx < KD) {
        const int m = idx >> 10;
        const int i = idx & (D - 1);
        g_wd[idx] = W[(size_t)i * KD + m * D + i];
    }
}

__global__ __launch_bounds__(THREADS, CTAS_PER_SM)
void imputation_kernel(const float* __restrict__ h_r,
                       const float* __restrict__ b,
                       float* __restrict__ out,
                       int n_rows) {
    __shared__ float4 wd4[K][THREADS];

    const int t = threadIdx.x;

    // --- PDL prologue: everything NOT depending on g_wd ---
    const float4 breg = reinterpret_cast<const float4*>(b)[t];
    const float4* __restrict__ h4 = reinterpret_cast<const float4*>(h_r);
    float4* __restrict__ o4 = reinterpret_cast<float4*>(out);

    // Wait for gather_wdiag_kernel to complete (PDL dependency).
    cudaGridDependencySynchronize();

    // Coalesced load of the pre-gathered diagonal (8 KB, L2-resident).
    const float4* gw4 = reinterpret_cast<const float4*>(g_wd);
    #pragma unroll
    for (int m = 0; m < K; m++) {
        wd4[m][t] = gw4[m * THREADS + t];
    }
    __syncthreads();

    // Persistent grid-stride over rows (608 CTAs, 4/SM everywhere).
    for (int n = blockIdx.x; n < n_rows; n += GRID) {
        const float4* __restrict__ hp = h4 + (size_t)n * (KD / 4);

        // 8 independent streaming (evict-first) loads in flight.
        float4 h[K];
        #pragma unroll
        for (int m = 0; m < K; m++) {
            h[m] = __ldcs(&hp[m * (D / 4) + t]);
        }

        float4 acc = breg;
        #pragma unroll
        for (int m = 0; m < K; m++) {
            const float4 w = wd4[m][t];   // LDS.128, conflict-free
            acc.x = fmaf(h[m].x, w.x, acc.x);
            acc.y = fmaf(h[m].y, w.y, acc.y);
            acc.z = fmaf(h[m].z, w.z, acc.z);
            acc.w = fmaf(h[m].w, w.w, acc.w);
        }

        // Cached write-back store: dirty line parks in L2, flushed in
        // bursts later instead of interleaving with the read stream.
        o4[(size_t)n * (D / 4) + t] = acc;
    }
}

extern "C" void kernel_launch(void* const* d_in, const int* in_sizes, int n_in,
                              void* d_out, int out_size) {
    const float* h_r = (const float*)d_in[0];
    const float* W   = (const float*)d_in[1];
    const float* b   = (const float*)d_in[2];
    float* out       = (float*)d_out;

    const int n_rows = in_sizes[0] / KD;   // 8192

    gather_wdiag_kernel<<<(KD + 255) / 256, 256>>>(W);

    // PDL: main kernel boots + runs g_wd-independent prologue while the
    // gather kernel finishes.
    cudaLaunchConfig_t cfg = {};
    cfg.gridDim = dim3(GRID, 1, 1);
    cfg.blockDim = dim3(THREADS, 1, 1);
    cfg.dynamicSmemBytes = 0;
    cfg.stream = 0;
    cudaLaunchAttribute attrs[1];
    attrs[0].id = cudaLaunchAttributeProgrammaticStreamSerialization;
    attrs[0].val.programmaticStreamSerializationAllowed = 1;
    cfg.attrs = attrs;
    cfg.numAttrs = 1;
    cudaLaunchKernelEx(&cfg, imputation_kernel, h_r, b, out, n_rows);
}